// round 6
// baseline (speedup 1.0000x reference)
#include <cuda_runtime.h>
#include <cuda_bf16.h>
#include <cstdint>
#include <math.h>

#define NQ      32768
#define KC      8192
#define DD      256
#define MT      64            // queries per CTA
#define NTILE   128           // codes per tile
#define NTILES  (KC / NTILE)  // 64
#define EPS     2e-6f

// ---------------- device scratch (no cudaMalloc) ----------------------------
__device__ float         g_cbsq[KC];
__device__ __nv_bfloat16 g_cb_hi[KC * DD];
__device__ __nv_bfloat16 g_cb_lo[KC * DD];
__device__ float         g_gap[NQ];

// ---------------- smem layout (bytes) ---------------------------------------
#define SM_A_HI  0                    // 4 chunks x (64 x 64 bf16) = 32 KB
#define SM_A_LO  32768                // 32 KB
#define SM_B     65536                // 2 stages x (hi 16KB + lo 16KB) = 64 KB
#define SM_CBSQ  131072               // 128 floats
#define SM_RD1   131584               // 64*4 floats
#define SM_RI1   132608               // 64*4 ints
#define SM_RD2   133632               // 64*4 floats
#define SM_TOTAL 134656

__device__ __forceinline__ uint32_t smem_u32(const void* p) {
    uint32_t a;
    asm("{ .reg .u64 t; cvta.to.shared.u64 t, %1; cvt.u32.u64 %0, t; }"
        : "=r"(a) : "l"(p));
    return a;
}
__device__ __forceinline__ uint32_t swz(uint32_t b) { return b ^ ((b >> 3) & 0x70); }

#define LDSM_X4(r0, r1, r2, r3, addr) \
    asm volatile("ldmatrix.sync.aligned.m8n8.x4.shared.b16 {%0,%1,%2,%3}, [%4];" \
                 : "=r"(r0), "=r"(r1), "=r"(r2), "=r"(r3) : "r"(addr))

#define MMA_BF16(c0, c1, c2, c3, a0, a1, a2, a3, b0, b1) \
    asm volatile("mma.sync.aligned.m16n8k16.row.col.f32.bf16.bf16.f32 " \
                 "{%0,%1,%2,%3}, {%4,%5,%6,%7}, {%8,%9}, {%0,%1,%2,%3};" \
                 : "+f"(c0), "+f"(c1), "+f"(c2), "+f"(c3) \
                 : "r"(a0), "r"(a1), "r"(a2), "r"(a3), "r"(b0), "r"(b1))

// ---------------------------------------------------------------------------
// Prep: split codebook to bf16 hi/lo + ||e||^2. One warp per code.
// ---------------------------------------------------------------------------
__global__ void prep_kernel(const float* __restrict__ cb) {
    int w = (blockIdx.x * blockDim.x + threadIdx.x) >> 5;
    int lane = threadIdx.x & 31;
    if (w >= KC) return;
    const float4* row = (const float4*)(cb + (size_t)w * DD);
    float s = 0.f;
    #pragma unroll
    for (int i = 0; i < 2; i++) {
        int f = lane + i * 32;
        float4 v = row[f];
        s += v.x * v.x + v.y * v.y + v.z * v.z + v.w * v.w;
        float xs[4] = {v.x, v.y, v.z, v.w};
        __nv_bfloat16 h[4], l[4];
        #pragma unroll
        for (int j = 0; j < 4; j++) {
            h[j] = __float2bfloat16_rn(xs[j]);
            l[j] = __float2bfloat16_rn(xs[j] - __bfloat162float(h[j]));
        }
        __nv_bfloat162 h0 = {h[0], h[1]}, h1 = {h[2], h[3]};
        __nv_bfloat162 l0 = {l[0], l[1]}, l1 = {l[2], l[3]};
        uint2 hu = {*(uint32_t*)&h0, *(uint32_t*)&h1};
        uint2 lu = {*(uint32_t*)&l0, *(uint32_t*)&l1};
        *(uint2*)(g_cb_hi + (size_t)w * DD + f * 4) = hu;
        *(uint2*)(g_cb_lo + (size_t)w * DD + f * 4) = lu;
    }
    #pragma unroll
    for (int off = 16; off; off >>= 1) s += __shfl_xor_sync(0xffffffffu, s, off);
    if (lane == 0) g_cbsq[w] = s;
}

// ---------------------------------------------------------------------------
// Main: HMMA bf16x3 GEMM + fused top-2 argmin.
// 256 threads = 8 warps (2M x 4N). CTA: 64 queries x all 8192 codes.
// ---------------------------------------------------------------------------
__global__ void __launch_bounds__(256, 1)
vq_mma_kernel(const float* __restrict__ z, float* __restrict__ out) {
    extern __shared__ char smem[];
    const uint32_t sb = smem_u32(smem);
    const int tid  = threadIdx.x;
    const int wid  = tid >> 5;
    const int lane = tid & 31;
    const int wm   = wid >> 2;     // 0..1
    const int wn   = wid & 3;      // 0..3
    const int qbase = blockIdx.x * MT;

    // ---- convert z tile (64x256 fp32) to swizzled hi/lo bf16 chunks --------
    #pragma unroll
    for (int i = 0; i < 16; i++) {
        int id = tid + i * 256;            // float4 id, 4096 total
        int row = id >> 6;                 // 64 float4 per row
        int col = (id & 63) * 4;           // bf16 col 0..252
        int ch  = col >> 6;
        int cl  = col & 63;
        float4 v = *(const float4*)(z + (size_t)(qbase + row) * DD + col);
        float xs[4] = {v.x, v.y, v.z, v.w};
        __nv_bfloat16 h[4], l[4];
        #pragma unroll
        for (int j = 0; j < 4; j++) {
            h[j] = __float2bfloat16_rn(xs[j]);
            l[j] = __float2bfloat16_rn(xs[j] - __bfloat162float(h[j]));
        }
        __nv_bfloat162 h0 = {h[0], h[1]}, h1 = {h[2], h[3]};
        __nv_bfloat162 l0 = {l[0], l[1]}, l1 = {l[2], l[3]};
        uint2 hu = {*(uint32_t*)&h0, *(uint32_t*)&h1};
        uint2 lu = {*(uint32_t*)&l0, *(uint32_t*)&l1};
        uint32_t o = swz((uint32_t)(row * 128 + cl * 2)) + ch * 8192;
        *(uint2*)(smem + SM_A_HI + o) = hu;
        *(uint2*)(smem + SM_A_LO + o) = lu;
    }

    // lane-derived fragment address components
    const int a_r  = wm * 32 + (lane & 15);
    const int a_c8 = (lane >> 4) * 8;
    const int b_r  = wn * 32 + (lane & 7) + ((lane >> 4) & 1) * 8;
    const int b_c8 = ((lane >> 3) & 1) * 8;

    // top-2 trackers: 4 row-slots per thread
    float t1d[4], t2d[4];
    int   t1i[4];
    #pragma unroll
    for (int s = 0; s < 4; s++) { t1d[s] = INFINITY; t2d[s] = INFINITY; t1i[s] = 0x7fffffff; }

    // B staging registers
    uint4 bh[4], bl[4];
    // preload tile0 chunk0
    #pragma unroll
    for (int i = 0; i < 4; i++) {
        int id = tid + i * 256;
        size_t src = (size_t)(id >> 3) * DD + (id & 7) * 8;
        bh[i] = *(const uint4*)(g_cb_hi + src);
        bl[i] = *(const uint4*)(g_cb_lo + src);
    }

    for (int tile = 0; tile < NTILES; tile++) {
        const int nbase = tile * NTILE;
        float acc[2][4][4] = {};

        #pragma unroll
        for (int dc = 0; dc < 4; dc++) {
            const int stage = dc & 1;
            __syncthreads();
            if (dc == 0 && tid < 128)
                ((float*)(smem + SM_CBSQ))[tid] = g_cbsq[nbase + tid];
            // store staged B chunk
            #pragma unroll
            for (int i = 0; i < 4; i++) {
                int id = tid + i * 256;
                uint32_t o = swz((uint32_t)((id >> 3) * 128 + (id & 7) * 16));
                *(uint4*)(smem + SM_B + stage * 32768 + o)         = bh[i];
                *(uint4*)(smem + SM_B + stage * 32768 + 16384 + o) = bl[i];
            }
            // prefetch next chunk (overlaps with MMA below)
            if (dc < 3 || tile < NTILES - 1) {
                int nnb = (dc < 3) ? nbase : nbase + NTILE;
                int ndc = (dc < 3) ? dc + 1 : 0;
                #pragma unroll
                for (int i = 0; i < 4; i++) {
                    int id = tid + i * 256;
                    size_t src = (size_t)(nnb + (id >> 3)) * DD + ndc * 64 + (id & 7) * 8;
                    bh[i] = *(const uint4*)(g_cb_hi + src);
                    bl[i] = *(const uint4*)(g_cb_lo + src);
                }
            }
            __syncthreads();

            const uint32_t a_hi_base = sb + SM_A_HI + dc * 8192;
            const uint32_t a_lo_base = sb + SM_A_LO + dc * 8192;
            const uint32_t b_hi_base = sb + SM_B + stage * 32768;
            const uint32_t b_lo_base = b_hi_base + 16384;

            #pragma unroll
            for (int k16 = 0; k16 < 4; k16++) {
                const int kc = k16 * 16;
                uint32_t ah[2][4], al[2][4], fh[2][4], fl[2][4];
                #pragma unroll
                for (int mt = 0; mt < 2; mt++) {
                    uint32_t o = swz((uint32_t)((a_r + mt * 16) * 128 + (a_c8 + kc) * 2));
                    LDSM_X4(ah[mt][0], ah[mt][1], ah[mt][2], ah[mt][3], a_hi_base + o);
                    LDSM_X4(al[mt][0], al[mt][1], al[mt][2], al[mt][3], a_lo_base + o);
                }
                #pragma unroll
                for (int np = 0; np < 2; np++) {
                    uint32_t o = swz((uint32_t)((b_r + np * 16) * 128 + (b_c8 + kc) * 2));
                    LDSM_X4(fh[np][0], fh[np][1], fh[np][2], fh[np][3], b_hi_base + o);
                    LDSM_X4(fl[np][0], fl[np][1], fl[np][2], fl[np][3], b_lo_base + o);
                }
                #pragma unroll
                for (int mt = 0; mt < 2; mt++)
                    #pragma unroll
                    for (int nt = 0; nt < 4; nt++) {
                        uint32_t bh0 = fh[nt >> 1][(nt & 1) * 2];
                        uint32_t bh1 = fh[nt >> 1][(nt & 1) * 2 + 1];
                        uint32_t bl0 = fl[nt >> 1][(nt & 1) * 2];
                        uint32_t bl1 = fl[nt >> 1][(nt & 1) * 2 + 1];
                        float* c = acc[mt][nt];
                        MMA_BF16(c[0], c[1], c[2], c[3],
                                 ah[mt][0], ah[mt][1], ah[mt][2], ah[mt][3], bh0, bh1);
                        MMA_BF16(c[0], c[1], c[2], c[3],
                                 al[mt][0], al[mt][1], al[mt][2], al[mt][3], bh0, bh1);
                        MMA_BF16(c[0], c[1], c[2], c[3],
                                 ah[mt][0], ah[mt][1], ah[mt][2], ah[mt][3], bl0, bl1);
                    }
            }
        }

        // ---- epilogue: dist + running top-2 --------------------------------
        const float* cbs = (const float*)(smem + SM_CBSQ);
        #pragma unroll
        for (int mt = 0; mt < 2; mt++)
            #pragma unroll
            for (int half = 0; half < 2; half++) {
                const int slot = mt * 2 + half;
                #pragma unroll
                for (int nt = 0; nt < 4; nt++) {
                    const int coll = wn * 32 + nt * 8 + (lane & 3) * 2;
                    #pragma unroll
                    for (int p = 0; p < 2; p++) {
                        float d = cbs[coll + p] - 2.0f * acc[mt][nt][half * 2 + p];
                        int gi = nbase + coll + p;
                        if (d < t1d[slot] || (d == t1d[slot] && gi < t1i[slot])) {
                            t2d[slot] = t1d[slot]; t1d[slot] = d; t1i[slot] = gi;
                        } else if (d < t2d[slot]) {
                            t2d[slot] = d;
                        }
                    }
                }
            }
    }

    // ---- lane-quad merge + cross-warp merge --------------------------------
    float* rd1 = (float*)(smem + SM_RD1);
    int*   ri1 = (int*)(smem + SM_RI1);
    float* rd2 = (float*)(smem + SM_RD2);
    #pragma unroll
    for (int slot = 0; slot < 4; slot++) {
        float d1 = t1d[slot], d2 = t2d[slot];
        int   i1 = t1i[slot];
        #pragma unroll
        for (int off = 1; off <= 2; off <<= 1) {
            float od1 = __shfl_xor_sync(0xffffffffu, d1, off);
            int   oi1 = __shfl_xor_sync(0xffffffffu, i1, off);
            float od2 = __shfl_xor_sync(0xffffffffu, d2, off);
            if (od1 < d1 || (od1 == d1 && oi1 < i1)) {
                d2 = fminf(d1, od2); d1 = od1; i1 = oi1;
            } else {
                d2 = fminf(d2, od1);
            }
        }
        if ((lane & 3) == 0) {
            int row = wm * 32 + (slot >> 1) * 16 + (slot & 1) * 8 + (lane >> 2);
            rd1[row * 4 + wn] = d1;
            ri1[row * 4 + wn] = i1;
            rd2[row * 4 + wn] = d2;
        }
    }
    __syncthreads();

    if (tid < MT) {
        float d1 = rd1[tid * 4], d2 = rd2[tid * 4];
        int   i1 = ri1[tid * 4];
        #pragma unroll
        for (int w = 1; w < 4; w++) {
            float od1 = rd1[tid * 4 + w], od2 = rd2[tid * 4 + w];
            int   oi1 = ri1[tid * 4 + w];
            if (od1 < d1 || (od1 == d1 && oi1 < i1)) {
                d2 = fminf(d1, od2); d1 = od1; i1 = oi1;
            } else {
                d2 = fminf(d2, od1);
            }
        }
        out[qbase + tid]   = (float)i1;
        g_gap[qbase + tid] = d2 - d1;
    }
}

// ---------------------------------------------------------------------------
// Rescue: exact fp32 re-scan (one warp per query) where top-2 gap < EPS.
// ---------------------------------------------------------------------------
__global__ void rescue_kernel(const float* __restrict__ z,
                              const float* __restrict__ cb,
                              float* __restrict__ out) {
    int q = (blockIdx.x * blockDim.x + threadIdx.x) >> 5;
    if (q >= NQ) return;
    if (g_gap[q] >= EPS) return;
    int lane = threadIdx.x & 31;

    float zr[8];
    #pragma unroll
    for (int i = 0; i < 8; i++) zr[i] = z[(size_t)q * DD + lane + i * 32];

    float bd = INFINITY;
    int   bi = 0;
    for (int n = 0; n < KC; n++) {
        const float* cr = cb + (size_t)n * DD;
        float dot = 0.f;
        #pragma unroll
        for (int i = 0; i < 8; i++) dot = fmaf(zr[i], cr[lane + i * 32], dot);
        #pragma unroll
        for (int off = 16; off; off >>= 1) dot += __shfl_xor_sync(0xffffffffu, dot, off);
        float dist = g_cbsq[n] - 2.0f * dot;
        if (dist < bd) { bd = dist; bi = n; }
    }
    if (lane == 0) out[q] = (float)bi;
}

// ---------------------------------------------------------------------------
extern "C" void kernel_launch(void* const* d_in, const int* in_sizes, int n_in,
                              void* d_out, int out_size) {
    // z_e_x is always the larger buffer (4x codebook).
    const float* z;
    const float* cb;
    if (in_sizes[0] >= in_sizes[1]) { z = (const float*)d_in[0]; cb = (const float*)d_in[1]; }
    else                            { cb = (const float*)d_in[0]; z = (const float*)d_in[1]; }
    float* out = (float*)d_out;

    cudaFuncSetAttribute(vq_mma_kernel,
                         cudaFuncAttributeMaxDynamicSharedMemorySize, SM_TOTAL);

    prep_kernel<<<KC / 8, 256>>>(cb);
    vq_mma_kernel<<<NQ / MT, 256, SM_TOTAL>>>(z, out);
    rescue_kernel<<<NQ / 8, 256>>>(z, cb, out);
}

// round 7
// speedup vs baseline: 2.3136x; 2.3136x over previous
#include <cuda_runtime.h>
#include <cuda_bf16.h>
#include <cstdint>
#include <math.h>

#define NQ      32768
#define KC      8192
#define DD      256
#define MT      128           // queries per CTA
#define NTILE   128           // codes per tile
#define NTILES  (KC / NTILE)  // 64
#define NSTAGES (NTILES * 4)  // 256 (64-dim chunks)
#define EPS     2e-6f

// ---------------- device scratch (no cudaMalloc) ----------------------------
__device__ float         g_cbsq[KC];
__device__ __nv_bfloat16 g_cb_hi[KC * DD];
__device__ __nv_bfloat16 g_cb_lo[KC * DD];
__device__ float         g_gap[NQ];

// ---------------- smem layout (bytes) ---------------------------------------
// A: 4 dc-chunks x (128 rows x 64 cols bf16, SW128) = 4 x 16KB, hi then lo
#define SM_A_HI  0
#define SM_A_LO  65536
#define SM_B     131072          // 2 stages x (hi 16KB + lo 16KB)
#define SM_RD1   196608          // 128*4 floats
#define SM_RI1   198656          // 128*4 ints
#define SM_RD2   200704          // 128*4 floats
#define SM_TOTAL 202752

__device__ __forceinline__ uint32_t smem_u32(const void* p) {
    uint32_t a;
    asm("{ .reg .u64 t; cvta.to.shared.u64 t, %1; cvt.u32.u64 %0, t; }"
        : "=r"(a) : "l"(p));
    return a;
}
__device__ __forceinline__ uint32_t swz(uint32_t b) { return b ^ ((b >> 3) & 0x70); }

#define LDSM_X4(r0, r1, r2, r3, addr) \
    asm volatile("ldmatrix.sync.aligned.m8n8.x4.shared.b16 {%0,%1,%2,%3}, [%4];" \
                 : "=r"(r0), "=r"(r1), "=r"(r2), "=r"(r3) : "r"(addr))

#define MMA_BF16(c0, c1, c2, c3, a0, a1, a2, a3, b0, b1) \
    asm volatile("mma.sync.aligned.m16n8k16.row.col.f32.bf16.bf16.f32 " \
                 "{%0,%1,%2,%3}, {%4,%5,%6,%7}, {%8,%9}, {%0,%1,%2,%3};" \
                 : "+f"(c0), "+f"(c1), "+f"(c2), "+f"(c3) \
                 : "r"(a0), "r"(a1), "r"(a2), "r"(a3), "r"(b0), "r"(b1))

#define CP16(dst, src) \
    asm volatile("cp.async.cg.shared.global [%0], [%1], 16;" :: "r"(dst), "l"(src))
#define CP_COMMIT() asm volatile("cp.async.commit_group;" ::: "memory")
#define CP_WAIT(n)  asm volatile("cp.async.wait_group %0;" :: "n"(n) : "memory")

// ---------------------------------------------------------------------------
// Prep: split codebook to bf16 hi/lo + ||e||^2. One warp per code.
// ---------------------------------------------------------------------------
__global__ void prep_kernel(const float* __restrict__ cb) {
    int w = (blockIdx.x * blockDim.x + threadIdx.x) >> 5;
    int lane = threadIdx.x & 31;
    if (w >= KC) return;
    const float4* row = (const float4*)(cb + (size_t)w * DD);
    float s = 0.f;
    #pragma unroll
    for (int i = 0; i < 2; i++) {
        int f = lane + i * 32;
        float4 v = row[f];
        s += v.x * v.x + v.y * v.y + v.z * v.z + v.w * v.w;
        float xs[4] = {v.x, v.y, v.z, v.w};
        __nv_bfloat16 h[4], l[4];
        #pragma unroll
        for (int j = 0; j < 4; j++) {
            h[j] = __float2bfloat16_rn(xs[j]);
            l[j] = __float2bfloat16_rn(xs[j] - __bfloat162float(h[j]));
        }
        __nv_bfloat162 h0 = {h[0], h[1]}, h1 = {h[2], h[3]};
        __nv_bfloat162 l0 = {l[0], l[1]}, l1 = {l[2], l[3]};
        uint2 hu = {*(uint32_t*)&h0, *(uint32_t*)&h1};
        uint2 lu = {*(uint32_t*)&l0, *(uint32_t*)&l1};
        *(uint2*)(g_cb_hi + (size_t)w * DD + f * 4) = hu;
        *(uint2*)(g_cb_lo + (size_t)w * DD + f * 4) = lu;
    }
    #pragma unroll
    for (int off = 16; off; off >>= 1) s += __shfl_xor_sync(0xffffffffu, s, off);
    if (lane == 0) g_cbsq[w] = s;
}

// ---------------------------------------------------------------------------
// Main: HMMA bf16x3 GEMM + fused top-2 argmin.
// 512 threads = 16 warps (4M x 4N). CTA: 128 queries x all 8192 codes.
// B streamed via cp.async double-buffer (hi+lo 32KB per 64-dim stage).
// ---------------------------------------------------------------------------
__global__ void __launch_bounds__(512, 1)
vq_mma_kernel(const float* __restrict__ z, float* __restrict__ out) {
    extern __shared__ char smem[];
    const uint32_t sb = smem_u32(smem);
    const int tid  = threadIdx.x;
    const int wid  = tid >> 5;
    const int lane = tid & 31;
    const int wm   = wid >> 2;     // 0..3
    const int wn   = wid & 3;      // 0..3
    const int qbase = blockIdx.x * MT;

    // ---- prefetch stage 0 of B (tile0, dc0) via cp.async -------------------
    {
        const uint32_t bst = sb + SM_B;   // stage 0
        #pragma unroll
        for (int i = 0; i < 2; i++) {
            int id  = tid + i * 512;               // 16B chunk id (1024)
            int row = id >> 3;
            int c8  = (id & 7) * 8;
            uint32_t o = swz((uint32_t)(row * 128 + c8 * 2));
            CP16(bst + o,         g_cb_hi + (size_t)row * DD + c8);
            CP16(bst + 16384 + o, g_cb_lo + (size_t)row * DD + c8);
        }
        CP_COMMIT();
    }

    // ---- convert z tile (128x256 fp32) to swizzled hi/lo bf16 chunks -------
    #pragma unroll
    for (int i = 0; i < 16; i++) {
        int id  = tid + i * 512;           // float4 id, 8192 total
        int row = id >> 6;
        int col = (id & 63) * 4;           // bf16 col 0..252
        int dc  = col >> 6;
        int cl  = col & 63;
        float4 v = *(const float4*)(z + (size_t)(qbase + row) * DD + col);
        float xs[4] = {v.x, v.y, v.z, v.w};
        __nv_bfloat16 h[4], l[4];
        #pragma unroll
        for (int j = 0; j < 4; j++) {
            h[j] = __float2bfloat16_rn(xs[j]);
            l[j] = __float2bfloat16_rn(xs[j] - __bfloat162float(h[j]));
        }
        __nv_bfloat162 h0 = {h[0], h[1]}, h1 = {h[2], h[3]};
        __nv_bfloat162 l0 = {l[0], l[1]}, l1 = {l[2], l[3]};
        uint2 hu = {*(uint32_t*)&h0, *(uint32_t*)&h1};
        uint2 lu = {*(uint32_t*)&l0, *(uint32_t*)&l1};
        uint32_t o = (uint32_t)(dc * 16384) + swz((uint32_t)(row * 128 + cl * 2));
        *(uint2*)(smem + SM_A_HI + o) = hu;
        *(uint2*)(smem + SM_A_LO + o) = lu;
    }

    // lane-derived fragment address components (validated in R6)
    const int a_r  = wm * 32 + (lane & 15);
    const int a_c8 = (lane >> 4) * 8;
    const int b_r  = wn * 32 + (lane & 7) + ((lane >> 4) & 1) * 8;
    const int b_c8 = ((lane >> 3) & 1) * 8;

    float t1d[4], t2d[4];
    int   t1i[4];
    #pragma unroll
    for (int s = 0; s < 4; s++) { t1d[s] = INFINITY; t2d[s] = INFINITY; t1i[s] = 0x7fffffff; }

    float acc[2][4][4] = {};

    for (int s = 0; s < NSTAGES; s++) {
        const int tile  = s >> 2;
        const int dc    = s & 3;
        const int stage = s & 1;

        // prefetch stage s+1
        if (s + 1 < NSTAGES) {
            const int nt_  = (s + 1) >> 2;
            const int ndc  = (s + 1) & 3;
            const uint32_t bst = sb + SM_B + ((s + 1) & 1) * 32768;
            #pragma unroll
            for (int i = 0; i < 2; i++) {
                int id  = tid + i * 512;
                int row = id >> 3;
                int c8  = (id & 7) * 8;
                uint32_t o = swz((uint32_t)(row * 128 + c8 * 2));
                size_t src = (size_t)(nt_ * NTILE + row) * DD + ndc * 64 + c8;
                CP16(bst + o,         g_cb_hi + src);
                CP16(bst + 16384 + o, g_cb_lo + src);
            }
            CP_COMMIT();
            CP_WAIT(1);
        } else {
            CP_WAIT(0);
        }
        __syncthreads();   // stage s data visible to all warps

        const uint32_t a_hi_base = sb + SM_A_HI + dc * 16384;
        const uint32_t a_lo_base = sb + SM_A_LO + dc * 16384;
        const uint32_t b_hi_base = sb + SM_B + stage * 32768;
        const uint32_t b_lo_base = b_hi_base + 16384;

        #pragma unroll
        for (int k16 = 0; k16 < 4; k16++) {
            const int kc = k16 * 16;
            uint32_t ah[2][4], al[2][4], fh[2][4], fl[2][4];
            #pragma unroll
            for (int mt = 0; mt < 2; mt++) {
                uint32_t o = swz((uint32_t)((a_r + mt * 16) * 128 + (a_c8 + kc) * 2));
                LDSM_X4(ah[mt][0], ah[mt][1], ah[mt][2], ah[mt][3], a_hi_base + o);
                LDSM_X4(al[mt][0], al[mt][1], al[mt][2], al[mt][3], a_lo_base + o);
            }
            #pragma unroll
            for (int np = 0; np < 2; np++) {
                uint32_t o = swz((uint32_t)((b_r + np * 16) * 128 + (b_c8 + kc) * 2));
                LDSM_X4(fh[np][0], fh[np][1], fh[np][2], fh[np][3], b_hi_base + o);
                LDSM_X4(fl[np][0], fl[np][1], fl[np][2], fl[np][3], b_lo_base + o);
            }
            #pragma unroll
            for (int mt = 0; mt < 2; mt++)
                #pragma unroll
                for (int nt = 0; nt < 4; nt++) {
                    uint32_t b0 = fh[nt >> 1][(nt & 1) * 2];
                    uint32_t b1 = fh[nt >> 1][(nt & 1) * 2 + 1];
                    uint32_t c0 = fl[nt >> 1][(nt & 1) * 2];
                    uint32_t c1 = fl[nt >> 1][(nt & 1) * 2 + 1];
                    float* c = acc[mt][nt];
                    MMA_BF16(c[0], c[1], c[2], c[3],
                             ah[mt][0], ah[mt][1], ah[mt][2], ah[mt][3], b0, b1);
                    MMA_BF16(c[0], c[1], c[2], c[3],
                             al[mt][0], al[mt][1], al[mt][2], al[mt][3], b0, b1);
                    MMA_BF16(c[0], c[1], c[2], c[3],
                             ah[mt][0], ah[mt][1], ah[mt][2], ah[mt][3], c0, c1);
                }
        }
        __syncthreads();   // all reads of stage s done before it is re-filled

        // ---- epilogue on tile boundary -------------------------------------
        if (dc == 3) {
            const int nbase = tile * NTILE;
            #pragma unroll
            for (int mt = 0; mt < 2; mt++)
                #pragma unroll
                for (int half = 0; half < 2; half++) {
                    const int slot = mt * 2 + half;
                    #pragma unroll
                    for (int nt = 0; nt < 4; nt++) {
                        const int coll = wn * 32 + nt * 8 + (lane & 3) * 2;
                        #pragma unroll
                        for (int p = 0; p < 2; p++) {
                            float cq = __ldg(&g_cbsq[nbase + coll + p]);
                            float d  = cq - 2.0f * acc[mt][nt][half * 2 + p];
                            int gi = nbase + coll + p;
                            if (d < t1d[slot] || (d == t1d[slot] && gi < t1i[slot])) {
                                t2d[slot] = t1d[slot]; t1d[slot] = d; t1i[slot] = gi;
                            } else if (d < t2d[slot]) {
                                t2d[slot] = d;
                            }
                        }
                    }
                }
            #pragma unroll
            for (int mt = 0; mt < 2; mt++)
                #pragma unroll
                for (int nt = 0; nt < 4; nt++)
                    #pragma unroll
                    for (int p = 0; p < 4; p++)
                        acc[mt][nt][p] = 0.f;
        }
    }

    // ---- lane-quad merge + cross-warp merge --------------------------------
    float* rd1 = (float*)(smem + SM_RD1);
    int*   ri1 = (int*)(smem + SM_RI1);
    float* rd2 = (float*)(smem + SM_RD2);
    #pragma unroll
    for (int slot = 0; slot < 4; slot++) {
        float d1 = t1d[slot], d2 = t2d[slot];
        int   i1 = t1i[slot];
        #pragma unroll
        for (int off = 1; off <= 2; off <<= 1) {
            float od1 = __shfl_xor_sync(0xffffffffu, d1, off);
            int   oi1 = __shfl_xor_sync(0xffffffffu, i1, off);
            float od2 = __shfl_xor_sync(0xffffffffu, d2, off);
            if (od1 < d1 || (od1 == d1 && oi1 < i1)) {
                d2 = fminf(d1, od2); d1 = od1; i1 = oi1;
            } else {
                d2 = fminf(d2, od1);
            }
        }
        if ((lane & 3) == 0) {
            int row = wm * 32 + (slot >> 1) * 16 + (slot & 1) * 8 + (lane >> 2);
            rd1[row * 4 + wn] = d1;
            ri1[row * 4 + wn] = i1;
            rd2[row * 4 + wn] = d2;
        }
    }
    __syncthreads();

    if (tid < MT) {
        float d1 = rd1[tid * 4], d2 = rd2[tid * 4];
        int   i1 = ri1[tid * 4];
        #pragma unroll
        for (int w = 1; w < 4; w++) {
            float od1 = rd1[tid * 4 + w], od2 = rd2[tid * 4 + w];
            int   oi1 = ri1[tid * 4 + w];
            if (od1 < d1 || (od1 == d1 && oi1 < i1)) {
                d2 = fminf(d1, od2); d1 = od1; i1 = oi1;
            } else {
                d2 = fminf(d2, od1);
            }
        }
        out[qbase + tid]   = (float)i1;
        g_gap[qbase + tid] = d2 - d1;
    }
}

// ---------------------------------------------------------------------------
// Rescue: exact fp32 re-scan, one 256-thread block per query (8 warps x 1024
// codes). Only blocks with small top-2 gap do work.
// ---------------------------------------------------------------------------
__global__ void rescue_kernel(const float* __restrict__ z,
                              const float* __restrict__ cb,
                              float* __restrict__ out) {
    const int q = blockIdx.x;
    if (g_gap[q] >= EPS) return;
    const int tid  = threadIdx.x;
    const int wid  = tid >> 5;
    const int lane = tid & 31;

    __shared__ float swd[8];
    __shared__ int   swi[8];

    float zr[8];
    #pragma unroll
    for (int i = 0; i < 8; i++) zr[i] = z[(size_t)q * DD + lane + i * 32];

    float bd = INFINITY;
    int   bi = 0x7fffffff;
    const int n0 = wid * (KC / 8);
    #pragma unroll 2
    for (int k = 0; k < KC / 8; k++) {
        const int n = n0 + k;
        const float* cr = cb + (size_t)n * DD;
        float dot = 0.f;
        #pragma unroll
        for (int i = 0; i < 8; i++) dot = fmaf(zr[i], cr[lane + i * 32], dot);
        #pragma unroll
        for (int off = 16; off; off >>= 1) dot += __shfl_xor_sync(0xffffffffu, dot, off);
        float dist = g_cbsq[n] - 2.0f * dot;
        if (dist < bd) { bd = dist; bi = n; }
    }
    if (lane == 0) { swd[wid] = bd; swi[wid] = bi; }
    __syncthreads();
    if (tid == 0) {
        float d = swd[0]; int i1 = swi[0];
        #pragma unroll
        for (int w = 1; w < 8; w++) {
            if (swd[w] < d || (swd[w] == d && swi[w] < i1)) { d = swd[w]; i1 = swi[w]; }
        }
        out[q] = (float)i1;
    }
}

// ---------------------------------------------------------------------------
extern "C" void kernel_launch(void* const* d_in, const int* in_sizes, int n_in,
                              void* d_out, int out_size) {
    // z_e_x is always the larger buffer (4x codebook).
    const float* z;
    const float* cb;
    if (in_sizes[0] >= in_sizes[1]) { z = (const float*)d_in[0]; cb = (const float*)d_in[1]; }
    else                            { cb = (const float*)d_in[0]; z = (const float*)d_in[1]; }
    float* out = (float*)d_out;

    cudaFuncSetAttribute(vq_mma_kernel,
                         cudaFuncAttributeMaxDynamicSharedMemorySize, SM_TOTAL);

    prep_kernel<<<KC / 8, 256>>>(cb);
    vq_mma_kernel<<<NQ / MT, 512, SM_TOTAL>>>(z, out);
    rescue_kernel<<<NQ, 256>>>(z, cb, out);
}